// round 14
// baseline (speedup 1.0000x reference)
#include <cuda_runtime.h>
#include <cuda_fp16.h>
#include <cstdint>

#define N_NODES 100000
#define E_MAX   1600000
#define IN_F    512
#define HID     128
#define NCLS    32

// ---------------- scratch (device globals; no allocation allowed) ------------
__device__ int    g_cnt[N_NODES];
__device__ int    g_rowstart[N_NODES];
__device__ int    g_cursor[N_NODES];
__device__ float  g_dinv[N_NODES];
__device__ int    g_col[E_MAX];
__device__ __half g_h1h[(size_t)N_NODES * HID];   // x @ W1 (fp16)
__device__ __half g_h2h[(size_t)N_NODES * NCLS];  // gcn1(x) @ W2 (fp16)
__device__ int    g_blocksums[128];
__device__ __half g_wh[HID * IN_F];               // W1^T fp16 [128][512]

__device__ __forceinline__ uint32_t smem_u32(const void* p) {
    uint32_t a;
    asm("{ .reg .u64 t; cvta.to.shared.u64 t, %1; cvt.u32.u64 %0, t; }"
        : "=r"(a) : "l"(p));
    return a;
}

__device__ __forceinline__ void ldsm_x4(uint32_t* r, uint32_t addr) {
    asm volatile("ldmatrix.sync.aligned.m8n8.x4.shared.b16 {%0,%1,%2,%3}, [%4];"
                 : "=r"(r[0]), "=r"(r[1]), "=r"(r[2]), "=r"(r[3]) : "r"(addr));
}

__device__ __forceinline__ void mma16816(float* d, const uint32_t* a, const uint32_t* b) {
    asm volatile(
        "mma.sync.aligned.m16n8k16.row.col.f32.f16.f16.f32 "
        "{%0,%1,%2,%3}, {%4,%5,%6,%7}, {%8,%9}, {%0,%1,%2,%3};"
        : "+f"(d[0]), "+f"(d[1]), "+f"(d[2]), "+f"(d[3])
        : "r"(a[0]), "r"(a[1]), "r"(a[2]), "r"(a[3]), "r"(b[0]), "r"(b[1]));
}

__device__ __forceinline__ void cpasync16(uint32_t dst, const void* src) {
    size_t g = __cvta_generic_to_global(src);
    asm volatile("cp.async.cg.shared.global [%0], [%1], 16;" :: "r"(dst), "l"(g));
}

// accumulate 8 fp16 feats (uint4) scaled by wgt into acc[8]
__device__ __forceinline__ void acc8_fn(float* acc, uint4 v, float wgt) {
    float2 f;
    f = __half22float2(*(__half2*)&v.x); acc[0] = fmaf(wgt, f.x, acc[0]); acc[1] = fmaf(wgt, f.y, acc[1]);
    f = __half22float2(*(__half2*)&v.y); acc[2] = fmaf(wgt, f.x, acc[2]); acc[3] = fmaf(wgt, f.y, acc[3]);
    f = __half22float2(*(__half2*)&v.z); acc[4] = fmaf(wgt, f.x, acc[4]); acc[5] = fmaf(wgt, f.y, acc[5]);
    f = __half22float2(*(__half2*)&v.w); acc[6] = fmaf(wgt, f.x, acc[6]); acc[7] = fmaf(wgt, f.y, acc[7]);
}

// accumulate 4 fp16 vals (uint2) scaled by wgt into acc[4]
__device__ __forceinline__ void acc4_fn(float* acc, uint2 v, float wgt) {
    float2 f0 = __half22float2(*(__half2*)&v.x);
    float2 f1 = __half22float2(*(__half2*)&v.y);
    acc[0] = fmaf(wgt, f0.x, acc[0]);
    acc[1] = fmaf(wgt, f0.y, acc[1]);
    acc[2] = fmaf(wgt, f1.x, acc[2]);
    acc[3] = fmaf(wgt, f1.y, acc[3]);
}

// ---------------- small helpers ------------------------------------------
__global__ void k_zero_cnt() {
    int i = blockIdx.x * blockDim.x + threadIdx.x;
    if (i < N_NODES) g_cnt[i] = 0;
}

__global__ void k_hist(const int* __restrict__ dst, int E) {
    int e = blockIdx.x * blockDim.x + threadIdx.x;
    if (e < E) atomicAdd(&g_cnt[dst[e]], 1);
}

// W1 [512][128] -> transpose + fp16 -> g_wh [128][512]
__global__ void k_prepw(const float* __restrict__ W1) {
    __shared__ float sh[32][33];
    int bi = blockIdx.x & 15;
    int bj = blockIdx.x >> 4;
    int k0 = bi * 32, n0 = bj * 32;
    int t = threadIdx.x;
    int i = t >> 5, j = t & 31;
#pragma unroll
    for (int r = 0; r < 4; r++) {
        int kk = i + r * 8;
        sh[kk][j] = W1[(size_t)(k0 + kk) * HID + n0 + j];
    }
    __syncthreads();
#pragma unroll
    for (int r = 0; r < 4; r++) {
        int nn = i + r * 8;
        g_wh[(size_t)(n0 + nn) * IN_F + k0 + j] = __float2half_rn(sh[j][nn]);
    }
}

__global__ void k_scan1() {
    __shared__ int sh[256];
    int b = blockIdx.x, t = threadIdx.x;
    int base = b * 1024 + t * 4;
    int v[4];
    int local = 0;
#pragma unroll
    for (int q = 0; q < 4; q++) {
        int i = base + q;
        v[q] = (i < N_NODES) ? g_cnt[i] : 0;
        local += v[q];
    }
    sh[t] = local;
    __syncthreads();
#pragma unroll
    for (int off = 1; off < 256; off <<= 1) {
        int add = (t >= off) ? sh[t - off] : 0;
        __syncthreads();
        sh[t] += add;
        __syncthreads();
    }
    int run = sh[t] - local;
    if (t == 255) g_blocksums[b] = sh[255];
#pragma unroll
    for (int q = 0; q < 4; q++) {
        int i = base + q;
        if (i < N_NODES) g_rowstart[i] = run;
        run += v[q];
    }
}

__global__ void k_scan2(int nblk) {
    __shared__ int sh[128];
    int t = threadIdx.x;
    int v = (t < nblk) ? g_blocksums[t] : 0;
    sh[t] = v;
    __syncthreads();
#pragma unroll
    for (int off = 1; off < 128; off <<= 1) {
        int add = (t >= off) ? sh[t - off] : 0;
        __syncthreads();
        sh[t] += add;
        __syncthreads();
    }
    if (t < nblk) g_blocksums[t] = sh[t] - v;
}

__global__ void k_scan3() {
    int i = blockIdx.x * blockDim.x + threadIdx.x;
    if (i >= N_NODES) return;
    int rs = g_rowstart[i] + g_blocksums[i >> 10];
    g_rowstart[i] = rs;
    g_cursor[i]   = rs;
    g_dinv[i]     = rsqrtf((float)(g_cnt[i] + 1));
}

__global__ void k_fill(const int* __restrict__ src, const int* __restrict__ dst, int E) {
    int e = blockIdx.x * blockDim.x + threadIdx.x;
    if (e >= E) return;
    int d = dst[e];
    int p = atomicAdd(&g_cursor[d], 1);
    g_col[p] = src[e];
}

// ---------------- GEMM1: h1 = X @ W1, single-pass fp16 mma (R9 proven) -------
#define G1_STAGE   20480
#define G1_SMEM    (2 * G1_STAGE)

__global__ __launch_bounds__(256, 2) void k_gemm1_mma(const float* __restrict__ X) {
    extern __shared__ char smem[];
    uint32_t sb = smem_u32(smem);

    const int tid  = threadIdx.x;
    const int wid  = tid >> 5;
    const int lane = tid & 31;
    const int bm   = blockIdx.x * 128;
    const int wm   = wid & 3;
    const int wn   = wid >> 2;

    const int arow_l = tid >> 1;
    const int ahalf  = tid & 1;
    int arow_g = bm + arow_l;
    if (arow_g >= N_NODES) arow_g = N_NODES - 1;
    const float* aptr = X + (size_t)arow_g * IN_F + ahalf * 16;

    float4 aR[4];

#define LDG_A(c) do { \
        const float4* p4 = (const float4*)(aptr + (c) * 32); \
        _Pragma("unroll") \
        for (int q = 0; q < 4; q++) aR[q] = p4[q]; \
    } while (0)

#define STS_A(s) do { \
        char* stg = smem + (s) * G1_STAGE; \
        uint32_t hw[8]; \
        _Pragma("unroll") \
        for (int q = 0; q < 4; q++) { \
            __half2 p0 = __float22half2_rn(make_float2(aR[q].x, aR[q].y)); \
            __half2 p1 = __float22half2_rn(make_float2(aR[q].z, aR[q].w)); \
            hw[2*q]   = *reinterpret_cast<uint32_t*>(&p0); \
            hw[2*q+1] = *reinterpret_cast<uint32_t*>(&p1); \
        } \
        uint4* a4 = (uint4*)(stg + arow_l * 80 + ahalf * 32); \
        a4[0] = make_uint4(hw[0], hw[1], hw[2], hw[3]); \
        a4[1] = make_uint4(hw[4], hw[5], hw[6], hw[7]); \
    } while (0)

#define CPA_B(c, s) do { \
        uint32_t bdst = sb + (s) * G1_STAGE + 10240; \
        _Pragma("unroll") \
        for (int q = 0; q < 2; q++) { \
            int u = tid + q * 256; \
            int row = u >> 2, j = u & 3; \
            cpasync16(bdst + row * 80 + j * 16, \
                      g_wh + (size_t)row * IN_F + (c) * 32 + j * 8); \
        } \
        asm volatile("cp.async.commit_group;"); \
    } while (0)

    float acc[2][8][4];
#pragma unroll
    for (int m = 0; m < 2; m++)
#pragma unroll
        for (int n = 0; n < 8; n++)
#pragma unroll
            for (int q = 0; q < 4; q++) acc[m][n][q] = 0.f;

    LDG_A(0);
    STS_A(0);
    CPA_B(0, 0);
    LDG_A(1);
    asm volatile("cp.async.wait_group 0;");
    __syncthreads();

    const int a_row  = wm * 32 + (lane & 15);
    const int a_koff = (lane >> 4) * 8;
    const int b_n    = wn * 64 + ((lane >> 4) & 1) * 8 + (lane & 7);
    const int b_koff = ((lane >> 3) & 1) * 8;

    for (int c = 0; c < 16; c++) {
        const int s = c & 1;
        uint32_t abase = sb + s * G1_STAGE;
        uint32_t bbase = abase + 10240;

#pragma unroll
        for (int ks = 0; ks < 2; ks++) {
            uint32_t ah[2][4];
#pragma unroll
            for (int m = 0; m < 2; m++) {
                uint32_t ad = abase + (uint32_t)((a_row + m * 16) * 80 + (a_koff + ks * 16) * 2);
                ldsm_x4(ah[m], ad);
            }
#pragma unroll
            for (int g = 0; g < 4; g++) {
                uint32_t bd = bbase + (uint32_t)((b_n + g * 16) * 80 + (b_koff + ks * 16) * 2);
                uint32_t rh[4];
                ldsm_x4(rh, bd);
#pragma unroll
                for (int m = 0; m < 2; m++) {
                    mma16816(acc[m][2*g],   ah[m], rh);
                    mma16816(acc[m][2*g+1], ah[m], rh + 2);
                }
            }
        }

        if (c < 15) {
            STS_A(s ^ 1);
            CPA_B(c + 1, s ^ 1);
            if (c < 14) LDG_A(c + 2);
            asm volatile("cp.async.wait_group 0;");
            __syncthreads();
        }
    }

    const int gid = lane >> 2, tig = lane & 3;
#pragma unroll
    for (int m = 0; m < 2; m++) {
        int r0 = bm + wm * 32 + m * 16 + gid;
#pragma unroll
        for (int n = 0; n < 8; n++) {
            int col = wn * 64 + n * 8 + tig * 2;
            if (r0 < N_NODES) {
                __half2 o = __floats2half2_rn(acc[m][n][0], acc[m][n][1]);
                *(__half2*)&g_h1h[(size_t)r0 * HID + col] = o;
            }
            if (r0 + 8 < N_NODES) {
                __half2 o = __floats2half2_rn(acc[m][n][2], acc[m][n][3]);
                *(__half2*)&g_h1h[(size_t)(r0 + 8) * HID + col] = o;
            }
        }
    }
#undef LDG_A
#undef STS_A
#undef CPA_B
}

// ---------------- Fused SpMM1 + GEMM2 (wide-gather, 1024-thread blocks) ------
// 32 warps/block -> W2s loaded 4x less often (L2 traffic 200 MB -> 50 MB).
__global__ __launch_bounds__(1024) void k_spmm1g2(const float* __restrict__ b1,
                                                  const float* __restrict__ W2) {
    __shared__ float W2s[HID * NCLS];       // 16 KB
    __shared__ float a1s[32][HID];          // 16 KB (per-warp row buffer)

    int t = threadIdx.x;
    if (t < 1024) {
        int f4 = t;
        *reinterpret_cast<float4*>(&W2s[f4 * 4]) =
            *reinterpret_cast<const float4*>(&W2[f4 * 4]);
    }
    __syncthreads();

    int warp = (blockIdx.x * blockDim.x + t) >> 5;
    int wi   = t >> 5;
    int lane = t & 31;
    if (warp >= N_NODES) return;
    int row   = warp;
    int start = g_rowstart[row];
    int cnt   = g_cnt[row];

    const uint4* H4 = reinterpret_cast<const uint4*>(g_h1h);   // 16 uint4/row
    const int* cp = g_col + start;
    const int hid_ = lane >> 4;    // 0/1 edge slot within pair
    const int fl   = lane & 15;    // feature group: feats fl*8..fl*8+7

    float acc[8];
#pragma unroll
    for (int j = 0; j < 8; j++) acc[j] = 0.f;

    int i = 0;
    for (; i + 8 <= cnt; i += 8) {               // 8 edges in flight
        int s0 = cp[i     + hid_];
        int s1 = cp[i + 2 + hid_];
        int s2 = cp[i + 4 + hid_];
        int s3 = cp[i + 6 + hid_];
        float w0 = g_dinv[s0], w1 = g_dinv[s1], w2 = g_dinv[s2], w3 = g_dinv[s3];
        uint4 v0 = H4[(size_t)s0 * 16 + fl];
        uint4 v1 = H4[(size_t)s1 * 16 + fl];
        uint4 v2 = H4[(size_t)s2 * 16 + fl];
        uint4 v3 = H4[(size_t)s3 * 16 + fl];
        acc8_fn(acc, v0, w0);
        acc8_fn(acc, v1, w1);
        acc8_fn(acc, v2, w2);
        acc8_fn(acc, v3, w3);
    }
    for (; i + 2 <= cnt; i += 2) {
        int s = cp[i + hid_];
        acc8_fn(acc, H4[(size_t)s * 16 + fl], g_dinv[s]);
    }
    if (i < cnt && hid_ == 0) {                  // odd tail: lower half only
        int s = cp[i];
        acc8_fn(acc, H4[(size_t)s * 16 + fl], g_dinv[s]);
    }

#pragma unroll
    for (int j = 0; j < 8; j++)
        acc[j] += __shfl_xor_sync(0xffffffffu, acc[j], 16);

    float d  = g_dinv[row];
    float dd = d * d;
    if (hid_ == 0) {
        uint4 hv = H4[(size_t)row * 16 + fl];
        float2 sf[4];
        sf[0] = __half22float2(*(__half2*)&hv.x);
        sf[1] = __half22float2(*(__half2*)&hv.y);
        sf[2] = __half22float2(*(__half2*)&hv.z);
        sf[3] = __half22float2(*(__half2*)&hv.w);
        float4 bb0 = reinterpret_cast<const float4*>(b1)[fl * 2];
        float4 bb1 = reinterpret_cast<const float4*>(b1)[fl * 2 + 1];
        float bv[8] = {bb0.x, bb0.y, bb0.z, bb0.w, bb1.x, bb1.y, bb1.z, bb1.w};
        float r[8];
#pragma unroll
        for (int j = 0; j < 8; j++) {
            float self = (j & 1) ? sf[j >> 1].y : sf[j >> 1].x;
            r[j] = fmaxf(fmaf(d, acc[j], dd * self) + bv[j], 0.f);
        }
        float4* dstp = reinterpret_cast<float4*>(&a1s[wi][fl * 8]);
        dstp[0] = make_float4(r[0], r[1], r[2], r[3]);
        dstp[1] = make_float4(r[4], r[5], r[6], r[7]);
    }
    __syncwarp();

    // mat-vec: each lane computes one class
    float o = 0.f;
#pragma unroll 8
    for (int k = 0; k < HID; k += 4) {
        float4 a4 = *reinterpret_cast<const float4*>(&a1s[wi][k]);
        o = fmaf(a4.x, W2s[(k + 0) * NCLS + lane], o);
        o = fmaf(a4.y, W2s[(k + 1) * NCLS + lane], o);
        o = fmaf(a4.z, W2s[(k + 2) * NCLS + lane], o);
        o = fmaf(a4.w, W2s[(k + 3) * NCLS + lane], o);
    }
    g_h2h[(size_t)row * NCLS + lane] = __float2half_rn(o);
}

// ---------------- SpMM layer 2 (wide-gather) ----------------------------------
__global__ void k_spmm2(const float* __restrict__ b2, float* __restrict__ out) {
    int warp = (blockIdx.x * blockDim.x + threadIdx.x) >> 5;
    int lane = threadIdx.x & 31;
    if (warp >= N_NODES) return;
    int row   = warp;
    int start = g_rowstart[row];
    int cnt   = g_cnt[row];
    const int* cp = g_col + start;

    const uint2* H2v = reinterpret_cast<const uint2*>(g_h2h);  // 8 uint2/row
    const int q  = lane >> 3;    // edge slot 0..3
    const int fl = lane & 7;     // classes fl*4..fl*4+3

    float acc[4] = {0.f, 0.f, 0.f, 0.f};

    int i = 0;
    for (; i + 8 <= cnt; i += 8) {              // 8 edges in flight
        int s0 = cp[i + q], s1 = cp[i + 4 + q];
        float w0 = g_dinv[s0], w1 = g_dinv[s1];
        uint2 v0 = H2v[(size_t)s0 * 8 + fl];
        uint2 v1 = H2v[(size_t)s1 * 8 + fl];
        acc4_fn(acc, v0, w0);
        acc4_fn(acc, v1, w1);
    }
    for (; i + 4 <= cnt; i += 4) {
        int s = cp[i + q];
        acc4_fn(acc, H2v[(size_t)s * 8 + fl], g_dinv[s]);
    }
    if (i < cnt) {                               // tail 1..3: slot-guarded
        int idx = i + q;
        if (idx < cnt) {
            int s = cp[idx];
            acc4_fn(acc, H2v[(size_t)s * 8 + fl], g_dinv[s]);
        }
    }

#pragma unroll
    for (int j = 0; j < 4; j++) {
        acc[j] += __shfl_xor_sync(0xffffffffu, acc[j], 8);
        acc[j] += __shfl_xor_sync(0xffffffffu, acc[j], 16);
    }

    float d = g_dinv[row];
    if (lane < 8) {
        uint2 hv = H2v[(size_t)row * 8 + fl];
        float2 s0 = __half22float2(*(__half2*)&hv.x);
        float2 s1 = __half22float2(*(__half2*)&hv.y);
        float4 bb = reinterpret_cast<const float4*>(b2)[fl];
        float dd = d * d;
        float4 r;
        r.x = fmaf(d, acc[0], dd * s0.x) + bb.x;
        r.y = fmaf(d, acc[1], dd * s0.y) + bb.y;
        r.z = fmaf(d, acc[2], dd * s1.x) + bb.z;
        r.w = fmaf(d, acc[3], dd * s1.y) + bb.w;
        reinterpret_cast<float4*>(out)[(size_t)row * 8 + fl] = r;
    }
}

// ---------------- launch ------------------------------------------------------
extern "C" void kernel_launch(void* const* d_in, const int* in_sizes, int n_in,
                              void* d_out, int out_size) {
    const float* x  = (const float*)d_in[0];
    const int*   ei = (const int*)d_in[1];
    const float* W1 = (const float*)d_in[2];
    const float* b1 = (const float*)d_in[3];
    const float* W2 = (const float*)d_in[4];
    const float* b2 = (const float*)d_in[5];
    float* out = (float*)d_out;

    int E = in_sizes[1] / 2;
    const int* src = ei;
    const int* dst = ei + E;

    int nScanBlocks = (N_NODES + 1023) / 1024;   // 98

    static cudaStream_t s2 = nullptr;
    static cudaEvent_t evFork = nullptr, evJoin = nullptr;
    static bool init_done = false;
    if (!init_done) {
        cudaFuncSetAttribute(k_gemm1_mma,
                             cudaFuncAttributeMaxDynamicSharedMemorySize,
                             G1_SMEM);
        cudaStreamCreateWithFlags(&s2, cudaStreamNonBlocking);
        cudaEventCreateWithFlags(&evFork, cudaEventDisableTiming);
        cudaEventCreateWithFlags(&evJoin, cudaEventDisableTiming);
        init_done = true;
    }

    // fork: CSR build on s2, GEMM path on the main (captured) stream.
    // Issue order puts exactly 5 kernels before k_gemm1_mma so that ncu's
    // "-s 5 -c 1" capture lands on the GEMM (diagnostic; no perf effect).
    k_prepw<<<64, 256>>>(W1);                                  // 1

    cudaEventRecord(evFork, 0);
    cudaStreamWaitEvent(s2, evFork, 0);

    k_zero_cnt<<<(N_NODES + 255) / 256, 256, 0, s2>>>();       // 2
    k_hist<<<(E + 255) / 256, 256, 0, s2>>>(dst, E);           // 3
    k_scan1<<<nScanBlocks, 256, 0, s2>>>();                    // 4
    k_scan2<<<1, 128, 0, s2>>>(nScanBlocks);                   // 5

    k_gemm1_mma<<<(N_NODES + 127) / 128, 256, G1_SMEM>>>(x);   // 6 <- profiled

    k_scan3<<<(N_NODES + 255) / 256, 256, 0, s2>>>();
    k_fill<<<(E + 255) / 256, 256, 0, s2>>>(src, dst, E);
    cudaEventRecord(evJoin, s2);

    // join
    cudaStreamWaitEvent(0, evJoin, 0);

    k_spmm1g2<<<(N_NODES + 31) / 32, 1024>>>(b1, W2);
    k_spmm2<<<(N_NODES + 7) / 8, 256>>>(b2, out);
}

// round 15
// speedup vs baseline: 1.0405x; 1.0405x over previous
#include <cuda_runtime.h>
#include <cuda_fp16.h>
#include <cstdint>

#define N_NODES 100000
#define E_MAX   1600000
#define IN_F    512
#define HID     128
#define NCLS    32

// ---------------- scratch (device globals; no allocation allowed) ------------
__device__ int    g_cnt[N_NODES];
__device__ int    g_rowstart[N_NODES];
__device__ int    g_cursor[N_NODES];
__device__ float  g_dinv[N_NODES];
__device__ int    g_col[E_MAX];
__device__ __half g_h1h[(size_t)N_NODES * HID];   // x @ W1 (fp16)
__device__ __half g_h2h[(size_t)N_NODES * NCLS];  // gcn1(x) @ W2 (fp16)
__device__ int    g_blocksums[128];
__device__ __half g_wh[HID * IN_F];               // W1^T fp16 [128][512]

__device__ __forceinline__ uint32_t smem_u32(const void* p) {
    uint32_t a;
    asm("{ .reg .u64 t; cvta.to.shared.u64 t, %1; cvt.u32.u64 %0, t; }"
        : "=r"(a) : "l"(p));
    return a;
}

__device__ __forceinline__ void ldsm_x4(uint32_t* r, uint32_t addr) {
    asm volatile("ldmatrix.sync.aligned.m8n8.x4.shared.b16 {%0,%1,%2,%3}, [%4];"
                 : "=r"(r[0]), "=r"(r[1]), "=r"(r[2]), "=r"(r[3]) : "r"(addr));
}

__device__ __forceinline__ void mma16816(float* d, const uint32_t* a, const uint32_t* b) {
    asm volatile(
        "mma.sync.aligned.m16n8k16.row.col.f32.f16.f16.f32 "
        "{%0,%1,%2,%3}, {%4,%5,%6,%7}, {%8,%9}, {%0,%1,%2,%3};"
        : "+f"(d[0]), "+f"(d[1]), "+f"(d[2]), "+f"(d[3])
        : "r"(a[0]), "r"(a[1]), "r"(a[2]), "r"(a[3]), "r"(b[0]), "r"(b[1]));
}

__device__ __forceinline__ void cpasync16(uint32_t dst, const void* src) {
    size_t g = __cvta_generic_to_global(src);
    asm volatile("cp.async.cg.shared.global [%0], [%1], 16;" :: "r"(dst), "l"(g));
}

// accumulate 8 fp16 feats (uint4) scaled by wgt into acc[8]
__device__ __forceinline__ void acc8_fn(float* acc, uint4 v, float wgt) {
    float2 f;
    f = __half22float2(*(__half2*)&v.x); acc[0] = fmaf(wgt, f.x, acc[0]); acc[1] = fmaf(wgt, f.y, acc[1]);
    f = __half22float2(*(__half2*)&v.y); acc[2] = fmaf(wgt, f.x, acc[2]); acc[3] = fmaf(wgt, f.y, acc[3]);
    f = __half22float2(*(__half2*)&v.z); acc[4] = fmaf(wgt, f.x, acc[4]); acc[5] = fmaf(wgt, f.y, acc[5]);
    f = __half22float2(*(__half2*)&v.w); acc[6] = fmaf(wgt, f.x, acc[6]); acc[7] = fmaf(wgt, f.y, acc[7]);
}

// accumulate 4 fp16 vals (uint2) scaled by wgt into acc[4]
__device__ __forceinline__ void acc4_fn(float* acc, uint2 v, float wgt) {
    float2 f0 = __half22float2(*(__half2*)&v.x);
    float2 f1 = __half22float2(*(__half2*)&v.y);
    acc[0] = fmaf(wgt, f0.x, acc[0]);
    acc[1] = fmaf(wgt, f0.y, acc[1]);
    acc[2] = fmaf(wgt, f1.x, acc[2]);
    acc[3] = fmaf(wgt, f1.y, acc[3]);
}

// ---------------- small helpers ------------------------------------------
__global__ void k_zero_cnt() {
    int i = blockIdx.x * blockDim.x + threadIdx.x;
    if (i < N_NODES) g_cnt[i] = 0;
}

__global__ void k_hist(const int* __restrict__ dst, int E) {
    int e = blockIdx.x * blockDim.x + threadIdx.x;
    if (e < E) atomicAdd(&g_cnt[dst[e]], 1);
}

// W1 [512][128] -> transpose + fp16 -> g_wh [128][512]
__global__ void k_prepw(const float* __restrict__ W1) {
    __shared__ float sh[32][33];
    int bi = blockIdx.x & 15;
    int bj = blockIdx.x >> 4;
    int k0 = bi * 32, n0 = bj * 32;
    int t = threadIdx.x;
    int i = t >> 5, j = t & 31;
#pragma unroll
    for (int r = 0; r < 4; r++) {
        int kk = i + r * 8;
        sh[kk][j] = W1[(size_t)(k0 + kk) * HID + n0 + j];
    }
    __syncthreads();
#pragma unroll
    for (int r = 0; r < 4; r++) {
        int nn = i + r * 8;
        g_wh[(size_t)(n0 + nn) * IN_F + k0 + j] = __float2half_rn(sh[j][nn]);
    }
}

__global__ void k_scan1() {
    __shared__ int sh[256];
    int b = blockIdx.x, t = threadIdx.x;
    int base = b * 1024 + t * 4;
    int v[4];
    int local = 0;
#pragma unroll
    for (int q = 0; q < 4; q++) {
        int i = base + q;
        v[q] = (i < N_NODES) ? g_cnt[i] : 0;
        local += v[q];
    }
    sh[t] = local;
    __syncthreads();
#pragma unroll
    for (int off = 1; off < 256; off <<= 1) {
        int add = (t >= off) ? sh[t - off] : 0;
        __syncthreads();
        sh[t] += add;
        __syncthreads();
    }
    int run = sh[t] - local;
    if (t == 255) g_blocksums[b] = sh[255];
#pragma unroll
    for (int q = 0; q < 4; q++) {
        int i = base + q;
        if (i < N_NODES) g_rowstart[i] = run;
        run += v[q];
    }
}

__global__ void k_scan2(int nblk) {
    __shared__ int sh[128];
    int t = threadIdx.x;
    int v = (t < nblk) ? g_blocksums[t] : 0;
    sh[t] = v;
    __syncthreads();
#pragma unroll
    for (int off = 1; off < 128; off <<= 1) {
        int add = (t >= off) ? sh[t - off] : 0;
        __syncthreads();
        sh[t] += add;
        __syncthreads();
    }
    if (t < nblk) g_blocksums[t] = sh[t] - v;
}

__global__ void k_scan3() {
    int i = blockIdx.x * blockDim.x + threadIdx.x;
    if (i >= N_NODES) return;
    int rs = g_rowstart[i] + g_blocksums[i >> 10];
    g_rowstart[i] = rs;
    g_cursor[i]   = rs;
    g_dinv[i]     = rsqrtf((float)(g_cnt[i] + 1));
}

__global__ void k_fill(const int* __restrict__ src, const int* __restrict__ dst, int E) {
    int e = blockIdx.x * blockDim.x + threadIdx.x;
    if (e >= E) return;
    int d = dst[e];
    int p = atomicAdd(&g_cursor[d], 1);
    g_col[p] = src[e];
}

// ---------------- GEMM1: h1 = X @ W1, single-pass fp16 mma (R9/R13 proven) ---
#define G1_STAGE   20480
#define G1_SMEM    (2 * G1_STAGE)

__global__ __launch_bounds__(256, 2) void k_gemm1_mma(const float* __restrict__ X) {
    extern __shared__ char smem[];
    uint32_t sb = smem_u32(smem);

    const int tid  = threadIdx.x;
    const int wid  = tid >> 5;
    const int lane = tid & 31;
    const int bm   = blockIdx.x * 128;
    const int wm   = wid & 3;
    const int wn   = wid >> 2;

    const int arow_l = tid >> 1;
    const int ahalf  = tid & 1;
    int arow_g = bm + arow_l;
    if (arow_g >= N_NODES) arow_g = N_NODES - 1;
    const float* aptr = X + (size_t)arow_g * IN_F + ahalf * 16;

    float4 aR[4];

#define LDG_A(c) do { \
        const float4* p4 = (const float4*)(aptr + (c) * 32); \
        _Pragma("unroll") \
        for (int q = 0; q < 4; q++) aR[q] = p4[q]; \
    } while (0)

#define STS_A(s) do { \
        char* stg = smem + (s) * G1_STAGE; \
        uint32_t hw[8]; \
        _Pragma("unroll") \
        for (int q = 0; q < 4; q++) { \
            __half2 p0 = __float22half2_rn(make_float2(aR[q].x, aR[q].y)); \
            __half2 p1 = __float22half2_rn(make_float2(aR[q].z, aR[q].w)); \
            hw[2*q]   = *reinterpret_cast<uint32_t*>(&p0); \
            hw[2*q+1] = *reinterpret_cast<uint32_t*>(&p1); \
        } \
        uint4* a4 = (uint4*)(stg + arow_l * 80 + ahalf * 32); \
        a4[0] = make_uint4(hw[0], hw[1], hw[2], hw[3]); \
        a4[1] = make_uint4(hw[4], hw[5], hw[6], hw[7]); \
    } while (0)

#define CPA_B(c, s) do { \
        uint32_t bdst = sb + (s) * G1_STAGE + 10240; \
        _Pragma("unroll") \
        for (int q = 0; q < 2; q++) { \
            int u = tid + q * 256; \
            int row = u >> 2, j = u & 3; \
            cpasync16(bdst + row * 80 + j * 16, \
                      g_wh + (size_t)row * IN_F + (c) * 32 + j * 8); \
        } \
        asm volatile("cp.async.commit_group;"); \
    } while (0)

    float acc[2][8][4];
#pragma unroll
    for (int m = 0; m < 2; m++)
#pragma unroll
        for (int n = 0; n < 8; n++)
#pragma unroll
            for (int q = 0; q < 4; q++) acc[m][n][q] = 0.f;

    LDG_A(0);
    STS_A(0);
    CPA_B(0, 0);
    LDG_A(1);
    asm volatile("cp.async.wait_group 0;");
    __syncthreads();

    const int a_row  = wm * 32 + (lane & 15);
    const int a_koff = (lane >> 4) * 8;
    const int b_n    = wn * 64 + ((lane >> 4) & 1) * 8 + (lane & 7);
    const int b_koff = ((lane >> 3) & 1) * 8;

#pragma unroll
    for (int c = 0; c < 16; c++) {
        const int s = c & 1;
        uint32_t abase = sb + s * G1_STAGE;
        uint32_t bbase = abase + 10240;

#pragma unroll
        for (int ks = 0; ks < 2; ks++) {
            uint32_t ah[2][4];
#pragma unroll
            for (int m = 0; m < 2; m++) {
                uint32_t ad = abase + (uint32_t)((a_row + m * 16) * 80 + (a_koff + ks * 16) * 2);
                ldsm_x4(ah[m], ad);
            }
#pragma unroll
            for (int g = 0; g < 4; g++) {
                uint32_t bd = bbase + (uint32_t)((b_n + g * 16) * 80 + (b_koff + ks * 16) * 2);
                uint32_t rh[4];
                ldsm_x4(rh, bd);
#pragma unroll
                for (int m = 0; m < 2; m++) {
                    mma16816(acc[m][2*g],   ah[m], rh);
                    mma16816(acc[m][2*g+1], ah[m], rh + 2);
                }
            }
        }

        if (c < 15) {
            STS_A(s ^ 1);
            CPA_B(c + 1, s ^ 1);
            if (c < 14) LDG_A(c + 2);
            asm volatile("cp.async.wait_group 0;");
            __syncthreads();
        }
    }

    const int gid = lane >> 2, tig = lane & 3;
#pragma unroll
    for (int m = 0; m < 2; m++) {
        int r0 = bm + wm * 32 + m * 16 + gid;
#pragma unroll
        for (int n = 0; n < 8; n++) {
            int col = wn * 64 + n * 8 + tig * 2;
            if (r0 < N_NODES) {
                __half2 o = __floats2half2_rn(acc[m][n][0], acc[m][n][1]);
                *(__half2*)&g_h1h[(size_t)r0 * HID + col] = o;
            }
            if (r0 + 8 < N_NODES) {
                __half2 o = __floats2half2_rn(acc[m][n][2], acc[m][n][3]);
                *(__half2*)&g_h1h[(size_t)(r0 + 8) * HID + col] = o;
            }
        }
    }
#undef LDG_A
#undef STS_A
#undef CPA_B
}

// ---------------- Fused SpMM1 + GEMM2 (wide-gather, 256-thread blocks) -------
__global__ __launch_bounds__(256) void k_spmm1g2(const float* __restrict__ b1,
                                                 const float* __restrict__ W2) {
    __shared__ float W2s[HID * NCLS];      // 16 KB
    __shared__ float a1s[8][HID];          // 4 KB

    int t = threadIdx.x;
#pragma unroll
    for (int q = 0; q < 4; q++) {
        int f4 = t + 256 * q;
        *reinterpret_cast<float4*>(&W2s[f4 * 4]) =
            *reinterpret_cast<const float4*>(&W2[f4 * 4]);
    }
    __syncthreads();

    int warp = (blockIdx.x * blockDim.x + t) >> 5;
    int wi   = t >> 5;
    int lane = t & 31;
    if (warp >= N_NODES) return;
    int row   = warp;
    int start = g_rowstart[row];
    int cnt   = g_cnt[row];

    const uint4* H4 = reinterpret_cast<const uint4*>(g_h1h);   // 16 uint4/row
    const int* cp = g_col + start;
    const int hid_ = lane >> 4;    // 0/1 edge slot within pair
    const int fl   = lane & 15;    // feature group: feats fl*8..fl*8+7

    float acc[8];
#pragma unroll
    for (int j = 0; j < 8; j++) acc[j] = 0.f;

    int i = 0;
    for (; i + 8 <= cnt; i += 8) {               // 8 edges in flight
        int s0 = cp[i     + hid_];
        int s1 = cp[i + 2 + hid_];
        int s2 = cp[i + 4 + hid_];
        int s3 = cp[i + 6 + hid_];
        float w0 = g_dinv[s0], w1 = g_dinv[s1], w2 = g_dinv[s2], w3 = g_dinv[s3];
        uint4 v0 = H4[(size_t)s0 * 16 + fl];
        uint4 v1 = H4[(size_t)s1 * 16 + fl];
        uint4 v2 = H4[(size_t)s2 * 16 + fl];
        uint4 v3 = H4[(size_t)s3 * 16 + fl];
        acc8_fn(acc, v0, w0);
        acc8_fn(acc, v1, w1);
        acc8_fn(acc, v2, w2);
        acc8_fn(acc, v3, w3);
    }
    for (; i + 2 <= cnt; i += 2) {
        int s = cp[i + hid_];
        acc8_fn(acc, H4[(size_t)s * 16 + fl], g_dinv[s]);
    }
    if (i < cnt && hid_ == 0) {                  // odd tail: lower half only
        int s = cp[i];
        acc8_fn(acc, H4[(size_t)s * 16 + fl], g_dinv[s]);
    }

#pragma unroll
    for (int j = 0; j < 8; j++)
        acc[j] += __shfl_xor_sync(0xffffffffu, acc[j], 16);

    float d  = g_dinv[row];
    float dd = d * d;
    if (hid_ == 0) {
        uint4 hv = H4[(size_t)row * 16 + fl];
        float2 sf[4];
        sf[0] = __half22float2(*(__half2*)&hv.x);
        sf[1] = __half22float2(*(__half2*)&hv.y);
        sf[2] = __half22float2(*(__half2*)&hv.z);
        sf[3] = __half22float2(*(__half2*)&hv.w);
        float4 bb0 = reinterpret_cast<const float4*>(b1)[fl * 2];
        float4 bb1 = reinterpret_cast<const float4*>(b1)[fl * 2 + 1];
        float bv[8] = {bb0.x, bb0.y, bb0.z, bb0.w, bb1.x, bb1.y, bb1.z, bb1.w};
        float r[8];
#pragma unroll
        for (int j = 0; j < 8; j++) {
            float self = (j & 1) ? sf[j >> 1].y : sf[j >> 1].x;
            r[j] = fmaxf(fmaf(d, acc[j], dd * self) + bv[j], 0.f);
        }
        float4* dstp = reinterpret_cast<float4*>(&a1s[wi][fl * 8]);
        dstp[0] = make_float4(r[0], r[1], r[2], r[3]);
        dstp[1] = make_float4(r[4], r[5], r[6], r[7]);
    }
    __syncwarp();

    // mat-vec: each lane computes one class
    float o = 0.f;
#pragma unroll 8
    for (int k = 0; k < HID; k += 4) {
        float4 a4 = *reinterpret_cast<const float4*>(&a1s[wi][k]);
        o = fmaf(a4.x, W2s[(k + 0) * NCLS + lane], o);
        o = fmaf(a4.y, W2s[(k + 1) * NCLS + lane], o);
        o = fmaf(a4.z, W2s[(k + 2) * NCLS + lane], o);
        o = fmaf(a4.w, W2s[(k + 3) * NCLS + lane], o);
    }
    g_h2h[(size_t)row * NCLS + lane] = __float2half_rn(o);
}

// ---------------- SpMM layer 2 (wide-gather) ----------------------------------
__global__ void k_spmm2(const float* __restrict__ b2, float* __restrict__ out) {
    int warp = (blockIdx.x * blockDim.x + threadIdx.x) >> 5;
    int lane = threadIdx.x & 31;
    if (warp >= N_NODES) return;
    int row   = warp;
    int start = g_rowstart[row];
    int cnt   = g_cnt[row];
    const int* cp = g_col + start;

    const uint2* H2v = reinterpret_cast<const uint2*>(g_h2h);  // 8 uint2/row
    const int q  = lane >> 3;    // edge slot 0..3
    const int fl = lane & 7;     // classes fl*4..fl*4+3

    float acc[4] = {0.f, 0.f, 0.f, 0.f};

    int i = 0;
    for (; i + 8 <= cnt; i += 8) {              // 8 edges in flight
        int s0 = cp[i + q], s1 = cp[i + 4 + q];
        float w0 = g_dinv[s0], w1 = g_dinv[s1];
        uint2 v0 = H2v[(size_t)s0 * 8 + fl];
        uint2 v1 = H2v[(size_t)s1 * 8 + fl];
        acc4_fn(acc, v0, w0);
        acc4_fn(acc, v1, w1);
    }
    for (; i + 4 <= cnt; i += 4) {
        int s = cp[i + q];
        acc4_fn(acc, H2v[(size_t)s * 8 + fl], g_dinv[s]);
    }
    if (i < cnt) {                               // tail 1..3: slot-guarded
        int idx = i + q;
        if (idx < cnt) {
            int s = cp[idx];
            acc4_fn(acc, H2v[(size_t)s * 8 + fl], g_dinv[s]);
        }
    }

#pragma unroll
    for (int j = 0; j < 4; j++) {
        acc[j] += __shfl_xor_sync(0xffffffffu, acc[j], 8);
        acc[j] += __shfl_xor_sync(0xffffffffu, acc[j], 16);
    }

    float d = g_dinv[row];
    if (lane < 8) {
        uint2 hv = H2v[(size_t)row * 8 + fl];
        float2 s0 = __half22float2(*(__half2*)&hv.x);
        float2 s1 = __half22float2(*(__half2*)&hv.y);
        float4 bb = reinterpret_cast<const float4*>(b2)[fl];
        float dd = d * d;
        float4 r;
        r.x = fmaf(d, acc[0], dd * s0.x) + bb.x;
        r.y = fmaf(d, acc[1], dd * s0.y) + bb.y;
        r.z = fmaf(d, acc[2], dd * s1.x) + bb.z;
        r.w = fmaf(d, acc[3], dd * s1.y) + bb.w;
        reinterpret_cast<float4*>(out)[(size_t)row * 8 + fl] = r;
    }
}

// ---------------- launch ------------------------------------------------------
extern "C" void kernel_launch(void* const* d_in, const int* in_sizes, int n_in,
                              void* d_out, int out_size) {
    const float* x  = (const float*)d_in[0];
    const int*   ei = (const int*)d_in[1];
    const float* W1 = (const float*)d_in[2];
    const float* b1 = (const float*)d_in[3];
    const float* W2 = (const float*)d_in[4];
    const float* b2 = (const float*)d_in[5];
    float* out = (float*)d_out;

    int E = in_sizes[1] / 2;
    const int* src = ei;
    const int* dst = ei + E;

    int nScanBlocks = (N_NODES + 1023) / 1024;   // 98

    static cudaStream_t s2 = nullptr;
    static cudaEvent_t evFork = nullptr, evJoin = nullptr;
    static bool init_done = false;
    if (!init_done) {
        cudaFuncSetAttribute(k_gemm1_mma,
                             cudaFuncAttributeMaxDynamicSharedMemorySize,
                             G1_SMEM);
        cudaStreamCreateWithFlags(&s2, cudaStreamNonBlocking);
        cudaEventCreateWithFlags(&evFork, cudaEventDisableTiming);
        cudaEventCreateWithFlags(&evJoin, cudaEventDisableTiming);
        init_done = true;
    }

    // fork: CSR build on s2, GEMM path on the main (captured) stream
    cudaEventRecord(evFork, 0);
    cudaStreamWaitEvent(s2, evFork, 0);

    k_zero_cnt<<<(N_NODES + 255) / 256, 256, 0, s2>>>();
    k_hist<<<(E + 255) / 256, 256, 0, s2>>>(dst, E);
    k_scan1<<<nScanBlocks, 256, 0, s2>>>();
    k_scan2<<<1, 128, 0, s2>>>(nScanBlocks);
    k_scan3<<<(N_NODES + 255) / 256, 256, 0, s2>>>();
    k_fill<<<(E + 255) / 256, 256, 0, s2>>>(src, dst, E);
    cudaEventRecord(evJoin, s2);

    k_prepw<<<64, 256>>>(W1);
    k_gemm1_mma<<<(N_NODES + 127) / 128, 256, G1_SMEM>>>(x);

    // join
    cudaStreamWaitEvent(0, evJoin, 0);

    k_spmm1g2<<<(N_NODES + 7) / 8, 256>>>(b1, W2);
    k_spmm2<<<(N_NODES + 7) / 8, 256>>>(b2, out);
}

// round 16
// speedup vs baseline: 1.0561x; 1.0149x over previous
#include <cuda_runtime.h>
#include <cuda_fp16.h>
#include <cstdint>

#define N_NODES 100000
#define E_MAX   1600000
#define IN_F    512
#define HID     128
#define NCLS    32

// ---------------- scratch (device globals; no allocation allowed) ------------
__device__ int    g_cnt[N_NODES];
__device__ int    g_rowstart[N_NODES];
__device__ int    g_cursor[N_NODES];
__device__ float  g_dinv[N_NODES];
__device__ int    g_col[E_MAX];
__device__ __half g_h1h[(size_t)N_NODES * HID];   // x @ W1 (fp16)
__device__ __half g_h2h[(size_t)N_NODES * NCLS];  // gcn1(x) @ W2 (fp16)
__device__ int    g_blocksums[128];
__device__ __half g_wh[HID * IN_F];               // W1^T fp16 [128][512]

__device__ __forceinline__ uint32_t smem_u32(const void* p) {
    uint32_t a;
    asm("{ .reg .u64 t; cvta.to.shared.u64 t, %1; cvt.u32.u64 %0, t; }"
        : "=r"(a) : "l"(p));
    return a;
}

__device__ __forceinline__ void ldsm_x4(uint32_t* r, uint32_t addr) {
    asm volatile("ldmatrix.sync.aligned.m8n8.x4.shared.b16 {%0,%1,%2,%3}, [%4];"
                 : "=r"(r[0]), "=r"(r[1]), "=r"(r[2]), "=r"(r[3]) : "r"(addr));
}

__device__ __forceinline__ void mma16816(float* d, const uint32_t* a, const uint32_t* b) {
    asm volatile(
        "mma.sync.aligned.m16n8k16.row.col.f32.f16.f16.f32 "
        "{%0,%1,%2,%3}, {%4,%5,%6,%7}, {%8,%9}, {%0,%1,%2,%3};"
        : "+f"(d[0]), "+f"(d[1]), "+f"(d[2]), "+f"(d[3])
        : "r"(a[0]), "r"(a[1]), "r"(a[2]), "r"(a[3]), "r"(b[0]), "r"(b[1]));
}

__device__ __forceinline__ void cpasync16(uint32_t dst, const void* src) {
    size_t g = __cvta_generic_to_global(src);
    asm volatile("cp.async.cg.shared.global [%0], [%1], 16;" :: "r"(dst), "l"(g));
}

// accumulate 8 fp16 feats (uint4) scaled by wgt into acc[8]
__device__ __forceinline__ void acc8_fn(float* acc, uint4 v, float wgt) {
    float2 f;
    f = __half22float2(*(__half2*)&v.x); acc[0] = fmaf(wgt, f.x, acc[0]); acc[1] = fmaf(wgt, f.y, acc[1]);
    f = __half22float2(*(__half2*)&v.y); acc[2] = fmaf(wgt, f.x, acc[2]); acc[3] = fmaf(wgt, f.y, acc[3]);
    f = __half22float2(*(__half2*)&v.z); acc[4] = fmaf(wgt, f.x, acc[4]); acc[5] = fmaf(wgt, f.y, acc[5]);
    f = __half22float2(*(__half2*)&v.w); acc[6] = fmaf(wgt, f.x, acc[6]); acc[7] = fmaf(wgt, f.y, acc[7]);
}

// accumulate 4 fp16 vals (uint2) scaled by wgt into acc[4]
__device__ __forceinline__ void acc4_fn(float* acc, uint2 v, float wgt) {
    float2 f0 = __half22float2(*(__half2*)&v.x);
    float2 f1 = __half22float2(*(__half2*)&v.y);
    acc[0] = fmaf(wgt, f0.x, acc[0]);
    acc[1] = fmaf(wgt, f0.y, acc[1]);
    acc[2] = fmaf(wgt, f1.x, acc[2]);
    acc[3] = fmaf(wgt, f1.y, acc[3]);
}

// ---------------- small helpers ------------------------------------------
__global__ void k_zero_cnt() {
    int i = blockIdx.x * blockDim.x + threadIdx.x;
    if (i < N_NODES) g_cnt[i] = 0;
}

__global__ void k_hist(const int* __restrict__ dst, int E) {
    int e = blockIdx.x * blockDim.x + threadIdx.x;
    if (e < E) atomicAdd(&g_cnt[dst[e]], 1);
}

// W1 [512][128] -> transpose + fp16 -> g_wh [128][512]
__global__ void k_prepw(const float* __restrict__ W1) {
    __shared__ float sh[32][33];
    int bi = blockIdx.x & 15;
    int bj = blockIdx.x >> 4;
    int k0 = bi * 32, n0 = bj * 32;
    int t = threadIdx.x;
    int i = t >> 5, j = t & 31;
#pragma unroll
    for (int r = 0; r < 4; r++) {
        int kk = i + r * 8;
        sh[kk][j] = W1[(size_t)(k0 + kk) * HID + n0 + j];
    }
    __syncthreads();
#pragma unroll
    for (int r = 0; r < 4; r++) {
        int nn = i + r * 8;
        g_wh[(size_t)(n0 + nn) * IN_F + k0 + j] = __float2half_rn(sh[j][nn]);
    }
}

__global__ void k_scan1() {
    __shared__ int sh[256];
    int b = blockIdx.x, t = threadIdx.x;
    int base = b * 1024 + t * 4;
    int v[4];
    int local = 0;
#pragma unroll
    for (int q = 0; q < 4; q++) {
        int i = base + q;
        v[q] = (i < N_NODES) ? g_cnt[i] : 0;
        local += v[q];
    }
    sh[t] = local;
    __syncthreads();
#pragma unroll
    for (int off = 1; off < 256; off <<= 1) {
        int add = (t >= off) ? sh[t - off] : 0;
        __syncthreads();
        sh[t] += add;
        __syncthreads();
    }
    int run = sh[t] - local;
    if (t == 255) g_blocksums[b] = sh[255];
#pragma unroll
    for (int q = 0; q < 4; q++) {
        int i = base + q;
        if (i < N_NODES) g_rowstart[i] = run;
        run += v[q];
    }
}

__global__ void k_scan2(int nblk) {
    __shared__ int sh[128];
    int t = threadIdx.x;
    int v = (t < nblk) ? g_blocksums[t] : 0;
    sh[t] = v;
    __syncthreads();
#pragma unroll
    for (int off = 1; off < 128; off <<= 1) {
        int add = (t >= off) ? sh[t - off] : 0;
        __syncthreads();
        sh[t] += add;
        __syncthreads();
    }
    if (t < nblk) g_blocksums[t] = sh[t] - v;
}

__global__ void k_scan3() {
    int i = blockIdx.x * blockDim.x + threadIdx.x;
    if (i >= N_NODES) return;
    int rs = g_rowstart[i] + g_blocksums[i >> 10];
    g_rowstart[i] = rs;
    g_cursor[i]   = rs;
    g_dinv[i]     = rsqrtf((float)(g_cnt[i] + 1));
}

__global__ void k_fill(const int* __restrict__ src, const int* __restrict__ dst, int E) {
    int e = blockIdx.x * blockDim.x + threadIdx.x;
    if (e >= E) return;
    int d = dst[e];
    int p = atomicAdd(&g_cursor[d], 1);
    g_col[p] = src[e];
}

// ---------------- GEMM1: h1 = X @ W1, single-pass fp16 mma (R13 config) ------
#define G1_STAGE   20480
#define G1_SMEM    (2 * G1_STAGE)

__global__ __launch_bounds__(256, 2) void k_gemm1_mma(const float* __restrict__ X) {
    extern __shared__ char smem[];
    uint32_t sb = smem_u32(smem);

    const int tid  = threadIdx.x;
    const int wid  = tid >> 5;
    const int lane = tid & 31;
    const int bm   = blockIdx.x * 128;
    const int wm   = wid & 3;
    const int wn   = wid >> 2;

    const int arow_l = tid >> 1;
    const int ahalf  = tid & 1;
    int arow_g = bm + arow_l;
    if (arow_g >= N_NODES) arow_g = N_NODES - 1;
    const float* aptr = X + (size_t)arow_g * IN_F + ahalf * 16;

    float4 aR[4];

#define LDG_A(c) do { \
        const float4* p4 = (const float4*)(aptr + (c) * 32); \
        _Pragma("unroll") \
        for (int q = 0; q < 4; q++) aR[q] = p4[q]; \
    } while (0)

#define STS_A(s) do { \
        char* stg = smem + (s) * G1_STAGE; \
        uint32_t hw[8]; \
        _Pragma("unroll") \
        for (int q = 0; q < 4; q++) { \
            __half2 p0 = __float22half2_rn(make_float2(aR[q].x, aR[q].y)); \
            __half2 p1 = __float22half2_rn(make_float2(aR[q].z, aR[q].w)); \
            hw[2*q]   = *reinterpret_cast<uint32_t*>(&p0); \
            hw[2*q+1] = *reinterpret_cast<uint32_t*>(&p1); \
        } \
        uint4* a4 = (uint4*)(stg + arow_l * 80 + ahalf * 32); \
        a4[0] = make_uint4(hw[0], hw[1], hw[2], hw[3]); \
        a4[1] = make_uint4(hw[4], hw[5], hw[6], hw[7]); \
    } while (0)

#define CPA_B(c, s) do { \
        uint32_t bdst = sb + (s) * G1_STAGE + 10240; \
        _Pragma("unroll") \
        for (int q = 0; q < 2; q++) { \
            int u = tid + q * 256; \
            int row = u >> 2, j = u & 3; \
            cpasync16(bdst + row * 80 + j * 16, \
                      g_wh + (size_t)row * IN_F + (c) * 32 + j * 8); \
        } \
        asm volatile("cp.async.commit_group;"); \
    } while (0)

    float acc[2][8][4];
#pragma unroll
    for (int m = 0; m < 2; m++)
#pragma unroll
        for (int n = 0; n < 8; n++)
#pragma unroll
            for (int q = 0; q < 4; q++) acc[m][n][q] = 0.f;

    LDG_A(0);
    STS_A(0);
    CPA_B(0, 0);
    LDG_A(1);
    asm volatile("cp.async.wait_group 0;");
    __syncthreads();

    const int a_row  = wm * 32 + (lane & 15);
    const int a_koff = (lane >> 4) * 8;
    const int b_n    = wn * 64 + ((lane >> 4) & 1) * 8 + (lane & 7);
    const int b_koff = ((lane >> 3) & 1) * 8;

#pragma unroll 2
    for (int c = 0; c < 16; c++) {
        const int s = c & 1;
        uint32_t abase = sb + s * G1_STAGE;
        uint32_t bbase = abase + 10240;

#pragma unroll
        for (int ks = 0; ks < 2; ks++) {
            uint32_t ah[2][4];
#pragma unroll
            for (int m = 0; m < 2; m++) {
                uint32_t ad = abase + (uint32_t)((a_row + m * 16) * 80 + (a_koff + ks * 16) * 2);
                ldsm_x4(ah[m], ad);
            }
#pragma unroll
            for (int g = 0; g < 4; g++) {
                uint32_t bd = bbase + (uint32_t)((b_n + g * 16) * 80 + (b_koff + ks * 16) * 2);
                uint32_t rh[4];
                ldsm_x4(rh, bd);
#pragma unroll
                for (int m = 0; m < 2; m++) {
                    mma16816(acc[m][2*g],   ah[m], rh);
                    mma16816(acc[m][2*g+1], ah[m], rh + 2);
                }
            }
        }

        if (c < 15) {
            STS_A(s ^ 1);
            CPA_B(c + 1, s ^ 1);
            if (c < 14) LDG_A(c + 2);
            asm volatile("cp.async.wait_group 0;");
            __syncthreads();
        }
    }

    const int gid = lane >> 2, tig = lane & 3;
#pragma unroll
    for (int m = 0; m < 2; m++) {
        int r0 = bm + wm * 32 + m * 16 + gid;
#pragma unroll
        for (int n = 0; n < 8; n++) {
            int col = wn * 64 + n * 8 + tig * 2;
            if (r0 < N_NODES) {
                __half2 o = __floats2half2_rn(acc[m][n][0], acc[m][n][1]);
                *(__half2*)&g_h1h[(size_t)r0 * HID + col] = o;
            }
            if (r0 + 8 < N_NODES) {
                __half2 o = __floats2half2_rn(acc[m][n][2], acc[m][n][3]);
                *(__half2*)&g_h1h[(size_t)(r0 + 8) * HID + col] = o;
            }
        }
    }
#undef LDG_A
#undef STS_A
#undef CPA_B
}

// ---------------- Fused SpMM1 + GEMM2 (wide-gather, 256-thread blocks) -------
__global__ __launch_bounds__(256) void k_spmm1g2(const float* __restrict__ b1,
                                                 const float* __restrict__ W2) {
    __shared__ float W2s[HID * NCLS];      // 16 KB
    __shared__ float a1s[8][HID];          // 4 KB

    int t = threadIdx.x;
#pragma unroll
    for (int q = 0; q < 4; q++) {
        int f4 = t + 256 * q;
        *reinterpret_cast<float4*>(&W2s[f4 * 4]) =
            *reinterpret_cast<const float4*>(&W2[f4 * 4]);
    }
    __syncthreads();

    int warp = (blockIdx.x * blockDim.x + t) >> 5;
    int wi   = t >> 5;
    int lane = t & 31;
    if (warp >= N_NODES) return;
    int row   = warp;
    int start = g_rowstart[row];
    int cnt   = g_cnt[row];

    const uint4* H4 = reinterpret_cast<const uint4*>(g_h1h);   // 16 uint4/row
    const int* cp = g_col + start;
    const int hid_ = lane >> 4;    // 0/1 edge slot within pair
    const int fl   = lane & 15;    // feature group: feats fl*8..fl*8+7

    float acc[8];
#pragma unroll
    for (int j = 0; j < 8; j++) acc[j] = 0.f;

    int i = 0;
    for (; i + 8 <= cnt; i += 8) {               // 8 edges in flight
        int s0 = cp[i     + hid_];
        int s1 = cp[i + 2 + hid_];
        int s2 = cp[i + 4 + hid_];
        int s3 = cp[i + 6 + hid_];
        float w0 = g_dinv[s0], w1 = g_dinv[s1], w2 = g_dinv[s2], w3 = g_dinv[s3];
        uint4 v0 = H4[(size_t)s0 * 16 + fl];
        uint4 v1 = H4[(size_t)s1 * 16 + fl];
        uint4 v2 = H4[(size_t)s2 * 16 + fl];
        uint4 v3 = H4[(size_t)s3 * 16 + fl];
        acc8_fn(acc, v0, w0);
        acc8_fn(acc, v1, w1);
        acc8_fn(acc, v2, w2);
        acc8_fn(acc, v3, w3);
    }
    for (; i + 2 <= cnt; i += 2) {
        int s = cp[i + hid_];
        acc8_fn(acc, H4[(size_t)s * 16 + fl], g_dinv[s]);
    }
    if (i < cnt && hid_ == 0) {                  // odd tail: lower half only
        int s = cp[i];
        acc8_fn(acc, H4[(size_t)s * 16 + fl], g_dinv[s]);
    }

#pragma unroll
    for (int j = 0; j < 8; j++)
        acc[j] += __shfl_xor_sync(0xffffffffu, acc[j], 16);

    float d  = g_dinv[row];
    float dd = d * d;
    if (hid_ == 0) {
        uint4 hv = H4[(size_t)row * 16 + fl];
        float2 sf[4];
        sf[0] = __half22float2(*(__half2*)&hv.x);
        sf[1] = __half22float2(*(__half2*)&hv.y);
        sf[2] = __half22float2(*(__half2*)&hv.z);
        sf[3] = __half22float2(*(__half2*)&hv.w);
        float4 bb0 = reinterpret_cast<const float4*>(b1)[fl * 2];
        float4 bb1 = reinterpret_cast<const float4*>(b1)[fl * 2 + 1];
        float bv[8] = {bb0.x, bb0.y, bb0.z, bb0.w, bb1.x, bb1.y, bb1.z, bb1.w};
        float r[8];
#pragma unroll
        for (int j = 0; j < 8; j++) {
            float self = (j & 1) ? sf[j >> 1].y : sf[j >> 1].x;
            r[j] = fmaxf(fmaf(d, acc[j], dd * self) + bv[j], 0.f);
        }
        float4* dstp = reinterpret_cast<float4*>(&a1s[wi][fl * 8]);
        dstp[0] = make_float4(r[0], r[1], r[2], r[3]);
        dstp[1] = make_float4(r[4], r[5], r[6], r[7]);
    }
    __syncwarp();

    // mat-vec: each lane computes one class
    float o = 0.f;
#pragma unroll 8
    for (int k = 0; k < HID; k += 4) {
        float4 a4 = *reinterpret_cast<const float4*>(&a1s[wi][k]);
        o = fmaf(a4.x, W2s[(k + 0) * NCLS + lane], o);
        o = fmaf(a4.y, W2s[(k + 1) * NCLS + lane], o);
        o = fmaf(a4.z, W2s[(k + 2) * NCLS + lane], o);
        o = fmaf(a4.w, W2s[(k + 3) * NCLS + lane], o);
    }
    g_h2h[(size_t)row * NCLS + lane] = __float2half_rn(o);
}

// ---------------- SpMM layer 2 (wide-gather) ----------------------------------
__global__ void k_spmm2(const float* __restrict__ b2, float* __restrict__ out) {
    int warp = (blockIdx.x * blockDim.x + threadIdx.x) >> 5;
    int lane = threadIdx.x & 31;
    if (warp >= N_NODES) return;
    int row   = warp;
    int start = g_rowstart[row];
    int cnt   = g_cnt[row];
    const int* cp = g_col + start;

    const uint2* H2v = reinterpret_cast<const uint2*>(g_h2h);  // 8 uint2/row
    const int q  = lane >> 3;    // edge slot 0..3
    const int fl = lane & 7;     // classes fl*4..fl*4+3

    float acc[4] = {0.f, 0.f, 0.f, 0.f};

    int i = 0;
    for (; i + 8 <= cnt; i += 8) {              // 8 edges in flight
        int s0 = cp[i + q], s1 = cp[i + 4 + q];
        float w0 = g_dinv[s0], w1 = g_dinv[s1];
        uint2 v0 = H2v[(size_t)s0 * 8 + fl];
        uint2 v1 = H2v[(size_t)s1 * 8 + fl];
        acc4_fn(acc, v0, w0);
        acc4_fn(acc, v1, w1);
    }
    for (; i + 4 <= cnt; i += 4) {
        int s = cp[i + q];
        acc4_fn(acc, H2v[(size_t)s * 8 + fl], g_dinv[s]);
    }
    if (i < cnt) {                               // tail 1..3: slot-guarded
        int idx = i + q;
        if (idx < cnt) {
            int s = cp[idx];
            acc4_fn(acc, H2v[(size_t)s * 8 + fl], g_dinv[s]);
        }
    }

#pragma unroll
    for (int j = 0; j < 4; j++) {
        acc[j] += __shfl_xor_sync(0xffffffffu, acc[j], 8);
        acc[j] += __shfl_xor_sync(0xffffffffu, acc[j], 16);
    }

    float d = g_dinv[row];
    if (lane < 8) {
        uint2 hv = H2v[(size_t)row * 8 + fl];
        float2 s0 = __half22float2(*(__half2*)&hv.x);
        float2 s1 = __half22float2(*(__half2*)&hv.y);
        float4 bb = reinterpret_cast<const float4*>(b2)[fl];
        float dd = d * d;
        float4 r;
        r.x = fmaf(d, acc[0], dd * s0.x) + bb.x;
        r.y = fmaf(d, acc[1], dd * s0.y) + bb.y;
        r.z = fmaf(d, acc[2], dd * s1.x) + bb.z;
        r.w = fmaf(d, acc[3], dd * s1.y) + bb.w;
        reinterpret_cast<float4*>(out)[(size_t)row * 8 + fl] = r;
    }
}

// ---------------- launch ------------------------------------------------------
extern "C" void kernel_launch(void* const* d_in, const int* in_sizes, int n_in,
                              void* d_out, int out_size) {
    const float* x  = (const float*)d_in[0];
    const int*   ei = (const int*)d_in[1];
    const float* W1 = (const float*)d_in[2];
    const float* b1 = (const float*)d_in[3];
    const float* W2 = (const float*)d_in[4];
    const float* b2 = (const float*)d_in[5];
    float* out = (float*)d_out;

    int E = in_sizes[1] / 2;
    const int* src = ei;
    const int* dst = ei + E;

    int nScanBlocks = (N_NODES + 1023) / 1024;   // 98

    static cudaStream_t s2 = nullptr;
    static cudaEvent_t evFork = nullptr, evJoin = nullptr;
    static bool init_done = false;
    if (!init_done) {
        cudaFuncSetAttribute(k_gemm1_mma,
                             cudaFuncAttributeMaxDynamicSharedMemorySize,
                             G1_SMEM);
        cudaStreamCreateWithFlags(&s2, cudaStreamNonBlocking);
        cudaEventCreateWithFlags(&evFork, cudaEventDisableTiming);
        cudaEventCreateWithFlags(&evJoin, cudaEventDisableTiming);
        init_done = true;
    }

    // fork: CSR build on s2, GEMM path on the main (captured) stream
    cudaEventRecord(evFork, 0);
    cudaStreamWaitEvent(s2, evFork, 0);

    k_zero_cnt<<<(N_NODES + 255) / 256, 256, 0, s2>>>();
    k_hist<<<(E + 255) / 256, 256, 0, s2>>>(dst, E);
    k_scan1<<<nScanBlocks, 256, 0, s2>>>();
    k_scan2<<<1, 128, 0, s2>>>(nScanBlocks);
    k_scan3<<<(N_NODES + 255) / 256, 256, 0, s2>>>();
    k_fill<<<(E + 255) / 256, 256, 0, s2>>>(src, dst, E);
    cudaEventRecord(evJoin, s2);

    k_prepw<<<64, 256>>>(W1);
    k_gemm1_mma<<<(N_NODES + 127) / 128, 256, G1_SMEM>>>(x);

    // join
    cudaStreamWaitEvent(0, evJoin, 0);

    k_spmm1g2<<<(N_NODES + 7) / 8, 256>>>(b1, W2);
    k_spmm2<<<(N_NODES + 7) / 8, 256>>>(b2, out);
}

// round 17
// speedup vs baseline: 1.0850x; 1.0274x over previous
#include <cuda_runtime.h>
#include <cuda_fp16.h>
#include <cstdint>

#define N_NODES 100000
#define E_MAX   1600000
#define IN_F    512
#define HID     128
#define NCLS    32

// ---------------- scratch (device globals; no allocation allowed) ------------
__device__ int    g_cnt[N_NODES];
__device__ int    g_rowstart[N_NODES];
__device__ int    g_cursor[N_NODES];
__device__ float  g_dinv[N_NODES];
__device__ int    g_col[E_MAX];
__device__ __half g_h1h[(size_t)N_NODES * HID];   // x @ W1 (fp16)
__device__ __half g_h2h[(size_t)N_NODES * NCLS];  // gcn1(x) @ W2 (fp16)
__device__ int    g_blocksums[128];
__device__ __half g_wh[HID * IN_F];               // W1^T fp16 [128][512]

__device__ __forceinline__ uint32_t smem_u32(const void* p) {
    uint32_t a;
    asm("{ .reg .u64 t; cvta.to.shared.u64 t, %1; cvt.u32.u64 %0, t; }"
        : "=r"(a) : "l"(p));
    return a;
}

__device__ __forceinline__ void ldsm_x4(uint32_t* r, uint32_t addr) {
    asm volatile("ldmatrix.sync.aligned.m8n8.x4.shared.b16 {%0,%1,%2,%3}, [%4];"
                 : "=r"(r[0]), "=r"(r[1]), "=r"(r[2]), "=r"(r[3]) : "r"(addr));
}

__device__ __forceinline__ void mma16816(float* d, const uint32_t* a, const uint32_t* b) {
    asm volatile(
        "mma.sync.aligned.m16n8k16.row.col.f32.f16.f16.f32 "
        "{%0,%1,%2,%3}, {%4,%5,%6,%7}, {%8,%9}, {%0,%1,%2,%3};"
        : "+f"(d[0]), "+f"(d[1]), "+f"(d[2]), "+f"(d[3])
        : "r"(a[0]), "r"(a[1]), "r"(a[2]), "r"(a[3]), "r"(b[0]), "r"(b[1]));
}

__device__ __forceinline__ void cpasync16(uint32_t dst, const void* src) {
    size_t g = __cvta_generic_to_global(src);
    asm volatile("cp.async.cg.shared.global [%0], [%1], 16;" :: "r"(dst), "l"(g));
}

// accumulate 8 fp16 feats (uint4) scaled by wgt into acc[8]
__device__ __forceinline__ void acc8_fn(float* acc, uint4 v, float wgt) {
    float2 f;
    f = __half22float2(*(__half2*)&v.x); acc[0] = fmaf(wgt, f.x, acc[0]); acc[1] = fmaf(wgt, f.y, acc[1]);
    f = __half22float2(*(__half2*)&v.y); acc[2] = fmaf(wgt, f.x, acc[2]); acc[3] = fmaf(wgt, f.y, acc[3]);
    f = __half22float2(*(__half2*)&v.z); acc[4] = fmaf(wgt, f.x, acc[4]); acc[5] = fmaf(wgt, f.y, acc[5]);
    f = __half22float2(*(__half2*)&v.w); acc[6] = fmaf(wgt, f.x, acc[6]); acc[7] = fmaf(wgt, f.y, acc[7]);
}

// accumulate 4 fp16 vals (uint2) scaled by wgt into acc[4]
__device__ __forceinline__ void acc4_fn(float* acc, uint2 v, float wgt) {
    float2 f0 = __half22float2(*(__half2*)&v.x);
    float2 f1 = __half22float2(*(__half2*)&v.y);
    acc[0] = fmaf(wgt, f0.x, acc[0]);
    acc[1] = fmaf(wgt, f0.y, acc[1]);
    acc[2] = fmaf(wgt, f1.x, acc[2]);
    acc[3] = fmaf(wgt, f1.y, acc[3]);
}

// ---------------- small helpers ------------------------------------------
__global__ void k_zero_cnt() {
    int i = blockIdx.x * blockDim.x + threadIdx.x;
    if (i < N_NODES) g_cnt[i] = 0;
}

__global__ void k_hist(const int* __restrict__ dst, int E) {
    int e = blockIdx.x * blockDim.x + threadIdx.x;
    if (e < E) atomicAdd(&g_cnt[dst[e]], 1);
}

// W1 [512][128] -> transpose + fp16 -> g_wh [128][512]
__global__ void k_prepw(const float* __restrict__ W1) {
    __shared__ float sh[32][33];
    int bi = blockIdx.x & 15;
    int bj = blockIdx.x >> 4;
    int k0 = bi * 32, n0 = bj * 32;
    int t = threadIdx.x;
    int i = t >> 5, j = t & 31;
#pragma unroll
    for (int r = 0; r < 4; r++) {
        int kk = i + r * 8;
        sh[kk][j] = W1[(size_t)(k0 + kk) * HID + n0 + j];
    }
    __syncthreads();
#pragma unroll
    for (int r = 0; r < 4; r++) {
        int nn = i + r * 8;
        g_wh[(size_t)(n0 + nn) * IN_F + k0 + j] = __float2half_rn(sh[j][nn]);
    }
}

__global__ void k_scan1() {
    __shared__ int sh[256];
    int b = blockIdx.x, t = threadIdx.x;
    int base = b * 1024 + t * 4;
    int v[4];
    int local = 0;
#pragma unroll
    for (int q = 0; q < 4; q++) {
        int i = base + q;
        v[q] = (i < N_NODES) ? g_cnt[i] : 0;
        local += v[q];
    }
    sh[t] = local;
    __syncthreads();
#pragma unroll
    for (int off = 1; off < 256; off <<= 1) {
        int add = (t >= off) ? sh[t - off] : 0;
        __syncthreads();
        sh[t] += add;
        __syncthreads();
    }
    int run = sh[t] - local;
    if (t == 255) g_blocksums[b] = sh[255];
#pragma unroll
    for (int q = 0; q < 4; q++) {
        int i = base + q;
        if (i < N_NODES) g_rowstart[i] = run;
        run += v[q];
    }
}

__global__ void k_scan2(int nblk) {
    __shared__ int sh[128];
    int t = threadIdx.x;
    int v = (t < nblk) ? g_blocksums[t] : 0;
    sh[t] = v;
    __syncthreads();
#pragma unroll
    for (int off = 1; off < 128; off <<= 1) {
        int add = (t >= off) ? sh[t - off] : 0;
        __syncthreads();
        sh[t] += add;
        __syncthreads();
    }
    if (t < nblk) g_blocksums[t] = sh[t] - v;
}

__global__ void k_scan3() {
    int i = blockIdx.x * blockDim.x + threadIdx.x;
    if (i >= N_NODES) return;
    int rs = g_rowstart[i] + g_blocksums[i >> 10];
    g_rowstart[i] = rs;
    g_cursor[i]   = rs;
    g_dinv[i]     = rsqrtf((float)(g_cnt[i] + 1));
}

__global__ void k_fill(const int* __restrict__ src, const int* __restrict__ dst, int E) {
    int e = blockIdx.x * blockDim.x + threadIdx.x;
    if (e >= E) return;
    int d = dst[e];
    int p = atomicAdd(&g_cursor[d], 1);
    g_col[p] = src[e];
}

// ---------------- GEMM1: h1 = X @ W1, single-pass fp16 mma (R13 config) ------
#define G1_STAGE   20480
#define G1_SMEM    (2 * G1_STAGE)

__global__ __launch_bounds__(256, 2) void k_gemm1_mma(const float* __restrict__ X) {
    extern __shared__ char smem[];
    uint32_t sb = smem_u32(smem);

    const int tid  = threadIdx.x;
    const int wid  = tid >> 5;
    const int lane = tid & 31;
    const int bm   = blockIdx.x * 128;
    const int wm   = wid & 3;
    const int wn   = wid >> 2;

    const int arow_l = tid >> 1;
    const int ahalf  = tid & 1;
    int arow_g = bm + arow_l;
    if (arow_g >= N_NODES) arow_g = N_NODES - 1;
    const float* aptr = X + (size_t)arow_g * IN_F + ahalf * 16;

    float4 aR[4];

#define LDG_A(c) do { \
        const float4* p4 = (const float4*)(aptr + (c) * 32); \
        _Pragma("unroll") \
        for (int q = 0; q < 4; q++) aR[q] = p4[q]; \
    } while (0)

#define STS_A(s) do { \
        char* stg = smem + (s) * G1_STAGE; \
        uint32_t hw[8]; \
        _Pragma("unroll") \
        for (int q = 0; q < 4; q++) { \
            __half2 p0 = __float22half2_rn(make_float2(aR[q].x, aR[q].y)); \
            __half2 p1 = __float22half2_rn(make_float2(aR[q].z, aR[q].w)); \
            hw[2*q]   = *reinterpret_cast<uint32_t*>(&p0); \
            hw[2*q+1] = *reinterpret_cast<uint32_t*>(&p1); \
        } \
        uint4* a4 = (uint4*)(stg + arow_l * 80 + ahalf * 32); \
        a4[0] = make_uint4(hw[0], hw[1], hw[2], hw[3]); \
        a4[1] = make_uint4(hw[4], hw[5], hw[6], hw[7]); \
    } while (0)

#define CPA_B(c, s) do { \
        uint32_t bdst = sb + (s) * G1_STAGE + 10240; \
        _Pragma("unroll") \
        for (int q = 0; q < 2; q++) { \
            int u = tid + q * 256; \
            int row = u >> 2, j = u & 3; \
            cpasync16(bdst + row * 80 + j * 16, \
                      g_wh + (size_t)row * IN_F + (c) * 32 + j * 8); \
        } \
        asm volatile("cp.async.commit_group;"); \
    } while (0)

    float acc[2][8][4];
#pragma unroll
    for (int m = 0; m < 2; m++)
#pragma unroll
        for (int n = 0; n < 8; n++)
#pragma unroll
            for (int q = 0; q < 4; q++) acc[m][n][q] = 0.f;

    LDG_A(0);
    STS_A(0);
    CPA_B(0, 0);
    LDG_A(1);
    asm volatile("cp.async.wait_group 0;");
    __syncthreads();

    const int a_row  = wm * 32 + (lane & 15);
    const int a_koff = (lane >> 4) * 8;
    const int b_n    = wn * 64 + ((lane >> 4) & 1) * 8 + (lane & 7);
    const int b_koff = ((lane >> 3) & 1) * 8;

    for (int c = 0; c < 16; c++) {
        const int s = c & 1;
        uint32_t abase = sb + s * G1_STAGE;
        uint32_t bbase = abase + 10240;

#pragma unroll
        for (int ks = 0; ks < 2; ks++) {
            uint32_t ah[2][4];
#pragma unroll
            for (int m = 0; m < 2; m++) {
                uint32_t ad = abase + (uint32_t)((a_row + m * 16) * 80 + (a_koff + ks * 16) * 2);
                ldsm_x4(ah[m], ad);
            }
#pragma unroll
            for (int g = 0; g < 4; g++) {
                uint32_t bd = bbase + (uint32_t)((b_n + g * 16) * 80 + (b_koff + ks * 16) * 2);
                uint32_t rh[4];
                ldsm_x4(rh, bd);
#pragma unroll
                for (int m = 0; m < 2; m++) {
                    mma16816(acc[m][2*g],   ah[m], rh);
                    mma16816(acc[m][2*g+1], ah[m], rh + 2);
                }
            }
        }

        if (c < 15) {
            STS_A(s ^ 1);
            CPA_B(c + 1, s ^ 1);
            if (c < 14) LDG_A(c + 2);
            asm volatile("cp.async.wait_group 0;");
            __syncthreads();
        }
    }

    const int gid = lane >> 2, tig = lane & 3;
#pragma unroll
    for (int m = 0; m < 2; m++) {
        int r0 = bm + wm * 32 + m * 16 + gid;
#pragma unroll
        for (int n = 0; n < 8; n++) {
            int col = wn * 64 + n * 8 + tig * 2;
            if (r0 < N_NODES) {
                __half2 o = __floats2half2_rn(acc[m][n][0], acc[m][n][1]);
                *(__half2*)&g_h1h[(size_t)r0 * HID + col] = o;
            }
            if (r0 + 8 < N_NODES) {
                __half2 o = __floats2half2_rn(acc[m][n][2], acc[m][n][3]);
                *(__half2*)&g_h1h[(size_t)(r0 + 8) * HID + col] = o;
            }
        }
    }
#undef LDG_A
#undef STS_A
#undef CPA_B
}

// ---------------- Fused SpMM1 + GEMM2 (wide-gather, 256-thread blocks) -------
__global__ __launch_bounds__(256) void k_spmm1g2(const float* __restrict__ b1,
                                                 const float* __restrict__ W2) {
    __shared__ float W2s[HID * NCLS];      // 16 KB
    __shared__ float a1s[8][HID];          // 4 KB

    int t = threadIdx.x;
#pragma unroll
    for (int q = 0; q < 4; q++) {
        int f4 = t + 256 * q;
        *reinterpret_cast<float4*>(&W2s[f4 * 4]) =
            *reinterpret_cast<const float4*>(&W2[f4 * 4]);
    }
    __syncthreads();

    int warp = (blockIdx.x * blockDim.x + t) >> 5;
    int wi   = t >> 5;
    int lane = t & 31;
    if (warp >= N_NODES) return;
    int row   = warp;
    int start = g_rowstart[row];
    int cnt   = g_cnt[row];

    const uint4* H4 = reinterpret_cast<const uint4*>(g_h1h);   // 16 uint4/row
    const int* cp = g_col + start;
    const int hid_ = lane >> 4;    // 0/1 edge slot within pair
    const int fl   = lane & 15;    // feature group: feats fl*8..fl*8+7

    float acc[8];
#pragma unroll
    for (int j = 0; j < 8; j++) acc[j] = 0.f;

    int i = 0;
    for (; i + 8 <= cnt; i += 8) {               // 8 edges in flight
        int s0 = cp[i     + hid_];
        int s1 = cp[i + 2 + hid_];
        int s2 = cp[i + 4 + hid_];
        int s3 = cp[i + 6 + hid_];
        float w0 = g_dinv[s0], w1 = g_dinv[s1], w2 = g_dinv[s2], w3 = g_dinv[s3];
        uint4 v0 = H4[(size_t)s0 * 16 + fl];
        uint4 v1 = H4[(size_t)s1 * 16 + fl];
        uint4 v2 = H4[(size_t)s2 * 16 + fl];
        uint4 v3 = H4[(size_t)s3 * 16 + fl];
        acc8_fn(acc, v0, w0);
        acc8_fn(acc, v1, w1);
        acc8_fn(acc, v2, w2);
        acc8_fn(acc, v3, w3);
    }
    for (; i + 2 <= cnt; i += 2) {
        int s = cp[i + hid_];
        acc8_fn(acc, H4[(size_t)s * 16 + fl], g_dinv[s]);
    }
    if (i < cnt && hid_ == 0) {                  // odd tail: lower half only
        int s = cp[i];
        acc8_fn(acc, H4[(size_t)s * 16 + fl], g_dinv[s]);
    }

#pragma unroll
    for (int j = 0; j < 8; j++)
        acc[j] += __shfl_xor_sync(0xffffffffu, acc[j], 16);

    float d  = g_dinv[row];
    float dd = d * d;
    if (hid_ == 0) {
        uint4 hv = H4[(size_t)row * 16 + fl];
        float2 sf[4];
        sf[0] = __half22float2(*(__half2*)&hv.x);
        sf[1] = __half22float2(*(__half2*)&hv.y);
        sf[2] = __half22float2(*(__half2*)&hv.z);
        sf[3] = __half22float2(*(__half2*)&hv.w);
        float4 bb0 = reinterpret_cast<const float4*>(b1)[fl * 2];
        float4 bb1 = reinterpret_cast<const float4*>(b1)[fl * 2 + 1];
        float bv[8] = {bb0.x, bb0.y, bb0.z, bb0.w, bb1.x, bb1.y, bb1.z, bb1.w};
        float r[8];
#pragma unroll
        for (int j = 0; j < 8; j++) {
            float self = (j & 1) ? sf[j >> 1].y : sf[j >> 1].x;
            r[j] = fmaxf(fmaf(d, acc[j], dd * self) + bv[j], 0.f);
        }
        float4* dstp = reinterpret_cast<float4*>(&a1s[wi][fl * 8]);
        dstp[0] = make_float4(r[0], r[1], r[2], r[3]);
        dstp[1] = make_float4(r[4], r[5], r[6], r[7]);
    }
    __syncwarp();

    // mat-vec: each lane computes one class
    float o = 0.f;
#pragma unroll 8
    for (int k = 0; k < HID; k += 4) {
        float4 a4 = *reinterpret_cast<const float4*>(&a1s[wi][k]);
        o = fmaf(a4.x, W2s[(k + 0) * NCLS + lane], o);
        o = fmaf(a4.y, W2s[(k + 1) * NCLS + lane], o);
        o = fmaf(a4.z, W2s[(k + 2) * NCLS + lane], o);
        o = fmaf(a4.w, W2s[(k + 3) * NCLS + lane], o);
    }
    g_h2h[(size_t)row * NCLS + lane] = __float2half_rn(o);
}

// ---------------- SpMM layer 2 (wide-gather) ----------------------------------
__global__ void k_spmm2(const float* __restrict__ b2, float* __restrict__ out) {
    int warp = (blockIdx.x * blockDim.x + threadIdx.x) >> 5;
    int lane = threadIdx.x & 31;
    if (warp >= N_NODES) return;
    int row   = warp;
    int start = g_rowstart[row];
    int cnt   = g_cnt[row];
    const int* cp = g_col + start;

    const uint2* H2v = reinterpret_cast<const uint2*>(g_h2h);  // 8 uint2/row
    const int q  = lane >> 3;    // edge slot 0..3
    const int fl = lane & 7;     // classes fl*4..fl*4+3

    float acc[4] = {0.f, 0.f, 0.f, 0.f};

    int i = 0;
    for (; i + 8 <= cnt; i += 8) {              // 8 edges in flight
        int s0 = cp[i + q], s1 = cp[i + 4 + q];
        float w0 = g_dinv[s0], w1 = g_dinv[s1];
        uint2 v0 = H2v[(size_t)s0 * 8 + fl];
        uint2 v1 = H2v[(size_t)s1 * 8 + fl];
        acc4_fn(acc, v0, w0);
        acc4_fn(acc, v1, w1);
    }
    for (; i + 4 <= cnt; i += 4) {
        int s = cp[i + q];
        acc4_fn(acc, H2v[(size_t)s * 8 + fl], g_dinv[s]);
    }
    if (i < cnt) {                               // tail 1..3: slot-guarded
        int idx = i + q;
        if (idx < cnt) {
            int s = cp[idx];
            acc4_fn(acc, H2v[(size_t)s * 8 + fl], g_dinv[s]);
        }
    }

#pragma unroll
    for (int j = 0; j < 4; j++) {
        acc[j] += __shfl_xor_sync(0xffffffffu, acc[j], 8);
        acc[j] += __shfl_xor_sync(0xffffffffu, acc[j], 16);
    }

    float d = g_dinv[row];
    if (lane < 8) {
        uint2 hv = H2v[(size_t)row * 8 + fl];
        float2 s0 = __half22float2(*(__half2*)&hv.x);
        float2 s1 = __half22float2(*(__half2*)&hv.y);
        float4 bb = reinterpret_cast<const float4*>(b2)[fl];
        float dd = d * d;
        float4 r;
        r.x = fmaf(d, acc[0], dd * s0.x) + bb.x;
        r.y = fmaf(d, acc[1], dd * s0.y) + bb.y;
        r.z = fmaf(d, acc[2], dd * s1.x) + bb.z;
        r.w = fmaf(d, acc[3], dd * s1.y) + bb.w;
        reinterpret_cast<float4*>(out)[(size_t)row * 8 + fl] = r;
    }
}

// ---------------- launch ------------------------------------------------------
extern "C" void kernel_launch(void* const* d_in, const int* in_sizes, int n_in,
                              void* d_out, int out_size) {
    const float* x  = (const float*)d_in[0];
    const int*   ei = (const int*)d_in[1];
    const float* W1 = (const float*)d_in[2];
    const float* b1 = (const float*)d_in[3];
    const float* W2 = (const float*)d_in[4];
    const float* b2 = (const float*)d_in[5];
    float* out = (float*)d_out;

    int E = in_sizes[1] / 2;
    const int* src = ei;
    const int* dst = ei + E;

    int nScanBlocks = (N_NODES + 1023) / 1024;   // 98

    static cudaStream_t s2 = nullptr;
    static cudaEvent_t evFork = nullptr, evJoin = nullptr;
    static bool init_done = false;
    if (!init_done) {
        cudaFuncSetAttribute(k_gemm1_mma,
                             cudaFuncAttributeMaxDynamicSharedMemorySize,
                             G1_SMEM);
        cudaStreamCreateWithFlags(&s2, cudaStreamNonBlocking);
        cudaEventCreateWithFlags(&evFork, cudaEventDisableTiming);
        cudaEventCreateWithFlags(&evJoin, cudaEventDisableTiming);
        init_done = true;
    }

    // fork: CSR build on s2, GEMM path on the main (captured) stream
    cudaEventRecord(evFork, 0);
    cudaStreamWaitEvent(s2, evFork, 0);

    k_zero_cnt<<<(N_NODES + 255) / 256, 256, 0, s2>>>();
    k_hist<<<(E + 255) / 256, 256, 0, s2>>>(dst, E);
    k_scan1<<<nScanBlocks, 256, 0, s2>>>();
    k_scan2<<<1, 128, 0, s2>>>(nScanBlocks);
    k_scan3<<<(N_NODES + 255) / 256, 256, 0, s2>>>();
    k_fill<<<(E + 255) / 256, 256, 0, s2>>>(src, dst, E);
    cudaEventRecord(evJoin, s2);

    k_prepw<<<64, 256>>>(W1);
    k_gemm1_mma<<<(N_NODES + 127) / 128, 256, G1_SMEM>>>(x);

    // join
    cudaStreamWaitEvent(0, evJoin, 0);

    k_spmm1g2<<<(N_NODES + 7) / 8, 256>>>(b1, W2);
    k_spmm2<<<(N_NODES + 7) / 8, 256>>>(b2, out);
}